// round 9
// baseline (speedup 1.0000x reference)
#include <cuda_runtime.h>
#include <cuda_bf16.h>

#define N_NODES 50000
#define N_EDGES_MAX 600000
#define D 128
#define N_CLASSES 40

#define SCAN_BLK 1024
#define SCAN_NBLK ((N_NODES + SCAN_BLK - 1) / SCAN_BLK)   // 49

// Scratch (static device globals — no allocations allowed).
// Only dereferenced from DEVICE code (host shadow deref is silent on GB300/ATS);
// host side only takes addresses via cudaGetSymbolAddress for memset.
__device__ float g_acc[N_NODES * D];   // gather output / GEMM input
__device__ float g_buf0[N_NODES * D];  // layer activations ping
__device__ float g_buf1[N_NODES * D];  // layer activations pong
__device__ int   g_cnt[N_NODES];       // in-degree histogram
__device__ int   g_row[N_NODES + 1];   // CSR row pointers (by dst)
__device__ int   g_cur[N_NODES];       // fill cursors
__device__ int   g_esrc[N_EDGES_MAX];  // CSR column indices (src nodes)
__device__ int   g_bsum[SCAN_NBLK];    // per-block scan totals

// ---------------------------------------------------------------------------
// CSR build
// ---------------------------------------------------------------------------
__global__ void gcn_hist_kernel(const int* __restrict__ dst, int n_edges) {
    int e = blockIdx.x * blockDim.x + threadIdx.x;
    if (e < n_edges) atomicAdd(&g_cnt[dst[e]], 1);
}

__global__ void gcn_scanA_kernel() {
    __shared__ int sh[SCAN_BLK];
    int t = threadIdx.x;
    int idx = blockIdx.x * SCAN_BLK + t;
    int v = (idx < N_NODES) ? g_cnt[idx] : 0;
    sh[t] = v;
    __syncthreads();
    for (int off = 1; off < SCAN_BLK; off <<= 1) {
        int u = (t >= off) ? sh[t - off] : 0;
        __syncthreads();
        sh[t] += u;
        __syncthreads();
    }
    if (idx < N_NODES) g_row[idx] = sh[t] - v;
    if (t == SCAN_BLK - 1) g_bsum[blockIdx.x] = sh[t];
}

// Pass B: block offset = prefix of g_bsum staged through smem (no serial L2 chain).
__global__ void gcn_scanB_kernel() {
    __shared__ int sh[64];
    __shared__ int s_off;
    int t = threadIdx.x;
    int blk = blockIdx.x;
    if (t < 64) sh[t] = (t < SCAN_NBLK) ? g_bsum[t] : 0;
    __syncthreads();
    if (t == 0) {
        int o = 0;
#pragma unroll 7
        for (int b = 0; b < blk; b++) o += sh[b];
        s_off = o;
    }
    __syncthreads();
    int off = s_off;
    int idx = blk * SCAN_BLK + t;
    if (idx < N_NODES) {
        int r = g_row[idx] + off;
        g_row[idx] = r;
        g_cur[idx] = r;
        if (idx == N_NODES - 1) g_row[N_NODES] = r + g_cnt[idx];
    }
}

__global__ void gcn_fill_kernel(const int* __restrict__ src,
                                const int* __restrict__ dst, int n_edges) {
    int e = blockIdx.x * blockDim.x + threadIdx.x;
    if (e < n_edges) {
        int pos = atomicAdd(&g_cur[dst[e]], 1);
        g_esrc[pos] = src[e];
    }
}

// ---------------------------------------------------------------------------
// Buffer selection by template (device-symbol addresses stay device-side).
// SEL: 0 = param pointer, 1 = g_buf0, 2 = g_buf1
// ---------------------------------------------------------------------------
template <int SEL>
__device__ __forceinline__ const float* sel_in(const float* p) {
    if (SEL == 0) return p;
    if (SEL == 1) return g_buf0;
    return g_buf1;
}
template <int SEL>
__device__ __forceinline__ float* sel_out(float* p) {
    if (SEL == 0) return p;
    if (SEL == 1) return g_buf0;
    return g_buf1;
}

// ---------------------------------------------------------------------------
// Gather: one warp per node. g_acc[n] = in[n] + sum_{s in nbrs(n)} in[s].
// No smem — high occupancy hides L2-hit latency.
// ---------------------------------------------------------------------------
template <int INSEL>
__global__ void gcn_gather_kernel(const float* __restrict__ in_p) {
    const float* in = sel_in<INSEL>(in_p);
    int node = blockIdx.x * (blockDim.x >> 5) + (threadIdx.x >> 5);
    if (node >= N_NODES) return;
    int lane = threadIdx.x & 31;
    int beg = g_row[node];
    int end = g_row[node + 1];
    float4 acc = *(const float4*)(in + (size_t)node * D + lane * 4);  // self
    int i = beg;
    for (; i + 4 <= end; i += 4) {
        int s0 = g_esrc[i], s1 = g_esrc[i + 1], s2 = g_esrc[i + 2], s3 = g_esrc[i + 3];
        float4 v0 = *(const float4*)(in + (size_t)s0 * D + lane * 4);
        float4 v1 = *(const float4*)(in + (size_t)s1 * D + lane * 4);
        float4 v2 = *(const float4*)(in + (size_t)s2 * D + lane * 4);
        float4 v3 = *(const float4*)(in + (size_t)s3 * D + lane * 4);
        acc.x += v0.x + v1.x + v2.x + v3.x;
        acc.y += v0.y + v1.y + v2.y + v3.y;
        acc.z += v0.z + v1.z + v2.z + v3.z;
        acc.w += v0.w + v1.w + v2.w + v3.w;
    }
    for (; i < end; i++) {
        int s = g_esrc[i];
        float4 v = *(const float4*)(in + (size_t)s * D + lane * 4);
        acc.x += v.x; acc.y += v.y; acc.z += v.z; acc.w += v.w;
    }
    *(float4*)(g_acc + (size_t)node * D + lane * 4) = acc;
}

// ---------------------------------------------------------------------------
// FFMA2 GEMM, K-paired: the f32x2 lanes carry (k even, k odd) partial sums for
// ONE output column. acc = lo+hi at the end. Benefits:
//  - a-operand (A[r][k],A[r][k+1]) contiguous in As -> LDS.128, no mov-pack
//  - b-operand (W[j][k],W[j][k+1]) contiguous in W  -> Bs is an UNtransposed
//    copy of W, b-loads are LDS.128 (2 k-pairs)
// Per 4 k-steps per thread: 4 LDS.128(a) + TN/4*8... for TN=8: 8 LDS.128(b)
// + 64 FFMA2  => ~19 issue slots per k (was 28).
// Thread map: tc = tid&15 -> cols j = tc + 16*jj; tr = tid>>4 -> rows tr*4+ii.
// ---------------------------------------------------------------------------
template <int OUTSEL, int BN, int TN, bool RELU>
__global__ __launch_bounds__(256, 2)
void gcn_gemm_kernel(const float* __restrict__ W,
                     const float* __restrict__ bias,
                     float* __restrict__ out_p,
                     int n_out, int ldo) {
    constexpr int BM = 64;
    constexpr int K = D;
    constexpr int LDA = K + 4;    // 132 floats (528B rows, 16B aligned)
    constexpr int LDK = K + 4;    // Bs row stride, same padding
    extern __shared__ float sm[];
    float* As = sm;               // [BM][LDA]   A rows (k-contiguous)
    float* Bs = sm + BM * LDA;    // [BN][LDK]   W rows (k-contiguous, no transpose)

    int tid = threadIdx.x;
    int row0 = blockIdx.x * BM;

    // W -> Bs straight copy (both k-contiguous): float4 coalesced.
    for (int i = tid * 4; i < BN * K; i += 256 * 4) {
        int j = i / K, k = i % K;
        float4 v = (j < n_out) ? *(const float4*)(W + (size_t)j * K + k)
                               : make_float4(0.f, 0.f, 0.f, 0.f);
        *(float4*)(Bs + j * LDK + k) = v;
    }
    // g_acc -> As (float4).
    for (int i = tid * 4; i < BM * K; i += 256 * 4) {
        int r = i / K, k = i % K;
        int g = row0 + r;
        float4 v = (g < N_NODES) ? *(const float4*)(g_acc + (size_t)g * K + k)
                                 : make_float4(0.f, 0.f, 0.f, 0.f);
        *(float4*)(As + r * LDA + k) = v;
    }
    __syncthreads();

    int tc = tid & 15;
    int tr = tid >> 4;

    unsigned long long acc[4][TN];   // (k-even, k-odd) partial-sum pairs
#pragma unroll
    for (int ii = 0; ii < 4; ii++)
#pragma unroll
        for (int jj = 0; jj < TN; jj++) acc[ii][jj] = 0ULL;

#pragma unroll 2
    for (int k = 0; k < K; k += 4) {
        ulonglong2 ap[4];
#pragma unroll
        for (int ii = 0; ii < 4; ii++)
            ap[ii] = *(const ulonglong2*)(As + (tr * 4 + ii) * LDA + k);
        // process jj in groups of 4 to bound live b registers
#pragma unroll
        for (int jg = 0; jg < TN; jg += 4) {
            ulonglong2 bp[4];
#pragma unroll
            for (int j4 = 0; j4 < 4; j4++)
                bp[j4] = *(const ulonglong2*)(Bs + (tc + 16 * (jg + j4)) * LDK + k);
#pragma unroll
            for (int ii = 0; ii < 4; ii++)
#pragma unroll
                for (int j4 = 0; j4 < 4; j4++) {
                    asm("fma.rn.f32x2 %0, %1, %2, %0;"
                        : "+l"(acc[ii][jg + j4]) : "l"(ap[ii].x), "l"(bp[j4].x));
                    asm("fma.rn.f32x2 %0, %1, %2, %0;"
                        : "+l"(acc[ii][jg + j4]) : "l"(ap[ii].y), "l"(bp[j4].y));
                }
        }
    }

    float* outp = sel_out<OUTSEL>(out_p);
#pragma unroll
    for (int ii = 0; ii < 4; ii++) {
        int g = row0 + tr * 4 + ii;
        if (g >= N_NODES) continue;
#pragma unroll
        for (int jj = 0; jj < TN; jj++) {
            int j = tc + 16 * jj;
            if (j >= n_out) continue;
            float lo, hi;
            asm("mov.b64 {%0, %1}, %2;" : "=f"(lo), "=f"(hi) : "l"(acc[ii][jj]));
            float v = lo + hi + __ldg(bias + j);
            if (RELU) v = fmaxf(v, 0.f);
            outp[(size_t)g * ldo + j] = v;
        }
    }
}

// ---------------------------------------------------------------------------
extern "C" void kernel_launch(void* const* d_in, const int* in_sizes, int n_in,
                              void* d_out, int out_size) {
    const float* x  = (const float*)d_in[0];
    const int* src  = (const int*)d_in[1];
    const int* dst  = (const int*)d_in[2];
    const float* W0 = (const float*)d_in[3];
    const float* b0 = (const float*)d_in[4];
    const float* W1 = (const float*)d_in[5];
    const float* b1 = (const float*)d_in[6];
    const float* W2 = (const float*)d_in[7];
    const float* b2 = (const float*)d_in[8];
    float* out = (float*)d_out;
    int n_edges = in_sizes[1];

    constexpr int SMEM_BIG   = (64 * 132 + 128 * 132) * 4;  // 101376 B -> 2 CTA/SM
    constexpr int SMEM_SMALL = (64 * 132 + 64 * 132) * 4;   //  67584 B
    static bool attr_done = false;
    if (!attr_done) {
        cudaFuncSetAttribute(gcn_gemm_kernel<1, 128, 8, true>,
                             cudaFuncAttributeMaxDynamicSharedMemorySize, SMEM_BIG);
        cudaFuncSetAttribute(gcn_gemm_kernel<2, 128, 8, true>,
                             cudaFuncAttributeMaxDynamicSharedMemorySize, SMEM_BIG);
        cudaFuncSetAttribute(gcn_gemm_kernel<0, 64, 4, false>,
                             cudaFuncAttributeMaxDynamicSharedMemorySize, SMEM_SMALL);
        attr_done = true;
    }

    // Zero the histogram with a capturable async memset (symbol address via API).
    void* cnt_ptr = nullptr;
    cudaGetSymbolAddress(&cnt_ptr, g_cnt);
    cudaMemsetAsync(cnt_ptr, 0, N_NODES * sizeof(int));

    int edge_blocks = (n_edges + 255) / 256;
    int gath_blocks = (N_NODES + 7) / 8;
    int gemm_blocks = (N_NODES + 63) / 64;

    // CSR build
    gcn_hist_kernel<<<edge_blocks, 256>>>(dst, n_edges);
    gcn_scanA_kernel<<<SCAN_NBLK, SCAN_BLK>>>();
    gcn_scanB_kernel<<<SCAN_NBLK, SCAN_BLK>>>();
    gcn_fill_kernel<<<edge_blocks, 256>>>(src, dst, n_edges);

    // Layer 0: x --gather--> g_acc --gemm--> g_buf0
    gcn_gather_kernel<0><<<gath_blocks, 256>>>(x);
    gcn_gemm_kernel<1, 128, 8, true><<<gemm_blocks, 256, SMEM_BIG>>>(
        W0, b0, nullptr, D, D);
    // Layer 1: g_buf0 --gather--> g_acc --gemm--> g_buf1
    gcn_gather_kernel<1><<<gath_blocks, 256>>>(nullptr);
    gcn_gemm_kernel<2, 128, 8, true><<<gemm_blocks, 256, SMEM_BIG>>>(
        W1, b1, nullptr, D, D);
    // Layer 2 (head): g_buf1 --gather--> g_acc --gemm--> out
    gcn_gather_kernel<2><<<gath_blocks, 256>>>(nullptr);
    gcn_gemm_kernel<0, 64, 4, false><<<gemm_blocks, 256, SMEM_SMALL>>>(
        W2, b2, out, N_CLASSES, N_CLASSES);
}

// round 11
// speedup vs baseline: 1.0665x; 1.0665x over previous
#include <cuda_runtime.h>
#include <cuda_bf16.h>
#include <cstdint>

#define N_NODES 50000
#define N_EDGES_MAX 600000
#define D 128
#define N_CLASSES 40

#define SCAN_BLK 1024
#define SCAN_NBLK ((N_NODES + SCAN_BLK - 1) / SCAN_BLK)   // 49

// Scratch (static device globals — no allocations allowed).
// Only dereferenced from DEVICE code; host only takes addresses via API.
__device__ float g_acc[N_NODES * D];   // z = h W^T (GEMM output / gather input)
__device__ float g_buf0[N_NODES * D];  // layer activations ping
__device__ float g_buf1[N_NODES * D];  // layer activations pong
__device__ int   g_cnt[N_NODES];
__device__ int   g_row[N_NODES + 1];
__device__ int   g_cur[N_NODES];
__device__ int   g_esrc[N_EDGES_MAX];
__device__ int   g_bsum[SCAN_NBLK];

// ---------------------------------------------------------------------------
// CSR build (4 edges per thread for MLP)
// ---------------------------------------------------------------------------
__global__ void gcn_hist_kernel(const int* __restrict__ dst, int n_edges) {
    int e0 = (blockIdx.x * blockDim.x + threadIdx.x) * 4;
    if (e0 + 3 < n_edges) {
        int4 d = *(const int4*)(dst + e0);
        atomicAdd(&g_cnt[d.x], 1);
        atomicAdd(&g_cnt[d.y], 1);
        atomicAdd(&g_cnt[d.z], 1);
        atomicAdd(&g_cnt[d.w], 1);
    } else {
        for (int e = e0; e < n_edges; e++) atomicAdd(&g_cnt[dst[e]], 1);
    }
}

__global__ void gcn_scanA_kernel() {
    __shared__ int sh[SCAN_BLK];
    int t = threadIdx.x;
    int idx = blockIdx.x * SCAN_BLK + t;
    int v = (idx < N_NODES) ? g_cnt[idx] : 0;
    sh[t] = v;
    __syncthreads();
    for (int off = 1; off < SCAN_BLK; off <<= 1) {
        int u = (t >= off) ? sh[t - off] : 0;
        __syncthreads();
        sh[t] += u;
        __syncthreads();
    }
    if (idx < N_NODES) g_row[idx] = sh[t] - v;
    if (t == SCAN_BLK - 1) g_bsum[blockIdx.x] = sh[t];
}

__global__ void gcn_scanB_kernel() {
    __shared__ int sh[64];
    __shared__ int s_off;
    int t = threadIdx.x;
    int blk = blockIdx.x;
    if (t < 64) sh[t] = (t < SCAN_NBLK) ? g_bsum[t] : 0;
    __syncthreads();
    if (t == 0) {
        int o = 0;
#pragma unroll 7
        for (int b = 0; b < blk; b++) o += sh[b];
        s_off = o;
    }
    __syncthreads();
    int off = s_off;
    int idx = blk * SCAN_BLK + t;
    if (idx < N_NODES) {
        int r = g_row[idx] + off;
        g_row[idx] = r;
        g_cur[idx] = r;
        if (idx == N_NODES - 1) g_row[N_NODES] = r + g_cnt[idx];
    }
}

__global__ void gcn_fill_kernel(const int* __restrict__ src,
                                const int* __restrict__ dst, int n_edges) {
    int e0 = (blockIdx.x * blockDim.x + threadIdx.x) * 4;
    if (e0 + 3 < n_edges) {
        int4 s = *(const int4*)(src + e0);
        int4 d = *(const int4*)(dst + e0);
        int p0 = atomicAdd(&g_cur[d.x], 1);
        int p1 = atomicAdd(&g_cur[d.y], 1);
        int p2 = atomicAdd(&g_cur[d.z], 1);
        int p3 = atomicAdd(&g_cur[d.w], 1);
        g_esrc[p0] = s.x; g_esrc[p1] = s.y; g_esrc[p2] = s.z; g_esrc[p3] = s.w;
    } else {
        for (int e = e0; e < n_edges; e++) {
            int pos = atomicAdd(&g_cur[dst[e]], 1);
            g_esrc[pos] = src[e];
        }
    }
}

// ---------------------------------------------------------------------------
// Buffer selection by template (device-symbol addresses stay device-side).
// SEL: 0 = param pointer, 1 = g_buf0, 2 = g_buf1
// ---------------------------------------------------------------------------
template <int SEL>
__device__ __forceinline__ const float* sel_in(const float* p) {
    if (SEL == 0) return p;
    if (SEL == 1) return g_buf0;
    return g_buf1;
}
template <int SEL>
__device__ __forceinline__ float* sel_out(float* p) {
    if (SEL == 0) return p;
    if (SEL == 1) return g_buf0;
    return g_buf1;
}

// ---------------------------------------------------------------------------
// GEMM (z = in @ W^T, NO bias/act — aggregation is commuted after it):
// K-paired FFMA2, 2 CTAs/SM. Writes z rows (width NOUT, stride NOUT) to g_acc.
// ---------------------------------------------------------------------------
template <int INSEL, int BN, int TN>
__global__ __launch_bounds__(256, 2)
void gcn_gemm_kernel(const float* __restrict__ in_p,
                     const float* __restrict__ W,
                     int n_out, int ldo) {
    constexpr int BM = 64;
    constexpr int K = D;
    constexpr int LDA = K + 4;
    constexpr int LDK = K + 4;
    extern __shared__ float sm[];
    float* As = sm;               // [BM][LDA]
    float* Bs = sm + BM * LDA;    // [BN][LDK] (W rows, k-contiguous)

    const float* in = sel_in<INSEL>(in_p);
    int tid = threadIdx.x;
    int row0 = blockIdx.x * BM;

    for (int i = tid * 4; i < BN * K; i += 256 * 4) {
        int j = i / K, k = i % K;
        float4 v = (j < n_out) ? *(const float4*)(W + (size_t)j * K + k)
                               : make_float4(0.f, 0.f, 0.f, 0.f);
        *(float4*)(Bs + j * LDK + k) = v;
    }
    for (int i = tid * 4; i < BM * K; i += 256 * 4) {
        int r = i / K, k = i % K;
        int g = row0 + r;
        float4 v = (g < N_NODES) ? *(const float4*)(in + (size_t)g * K + k)
                                 : make_float4(0.f, 0.f, 0.f, 0.f);
        *(float4*)(As + r * LDA + k) = v;
    }
    __syncthreads();

    int tc = tid & 15;
    int tr = tid >> 4;

    unsigned long long acc[4][TN];
#pragma unroll
    for (int ii = 0; ii < 4; ii++)
#pragma unroll
        for (int jj = 0; jj < TN; jj++) acc[ii][jj] = 0ULL;

#pragma unroll 2
    for (int k = 0; k < K; k += 4) {
        ulonglong2 ap[4];
#pragma unroll
        for (int ii = 0; ii < 4; ii++)
            ap[ii] = *(const ulonglong2*)(As + (tr * 4 + ii) * LDA + k);
#pragma unroll
        for (int jg = 0; jg < TN; jg += 4) {
            ulonglong2 bp[4];
#pragma unroll
            for (int j4 = 0; j4 < 4; j4++)
                bp[j4] = *(const ulonglong2*)(Bs + (tc + 16 * (jg + j4)) * LDK + k);
#pragma unroll
            for (int ii = 0; ii < 4; ii++)
#pragma unroll
                for (int j4 = 0; j4 < 4; j4++) {
                    asm("fma.rn.f32x2 %0, %1, %2, %0;"
                        : "+l"(acc[ii][jg + j4]) : "l"(ap[ii].x), "l"(bp[j4].x));
                    asm("fma.rn.f32x2 %0, %1, %2, %0;"
                        : "+l"(acc[ii][jg + j4]) : "l"(ap[ii].y), "l"(bp[j4].y));
                }
        }
    }

#pragma unroll
    for (int ii = 0; ii < 4; ii++) {
        int g = row0 + tr * 4 + ii;
        if (g >= N_NODES) continue;
#pragma unroll
        for (int jj = 0; jj < TN; jj++) {
            int j = tc + 16 * jj;
            if (j >= n_out) continue;
            float lo, hi;
            asm("mov.b64 {%0, %1}, %2;" : "=f"(lo), "=f"(hi) : "l"(acc[ii][jj]));
            g_acc[(size_t)g * ldo + j] = lo + hi;
        }
    }
}

// ---------------------------------------------------------------------------
// Gather over z = hW^T, fused bias + activation:
//   out[n] = act( z[n] + sum_{s in nbrs(n)} z[s] + b )
// NOUT = 128 (hidden, 32 lanes x float4) or 40 (head, lanes 0..9 active).
// ---------------------------------------------------------------------------
template <int OUTSEL, int NOUT, bool RELU>
__global__ void gcn_gather_kernel(const float* __restrict__ bias,
                                  float* __restrict__ out_p) {
    constexpr int NV = NOUT / 4;   // active float4 lanes per row
    int node = blockIdx.x * (blockDim.x >> 5) + (threadIdx.x >> 5);
    if (node >= N_NODES) return;
    int lane = threadIdx.x & 31;
    bool act = (NV == 32) || (lane < NV);
    int beg = g_row[node];
    int end = g_row[node + 1];

    float4 acc = make_float4(0.f, 0.f, 0.f, 0.f);
    float4 bv = make_float4(0.f, 0.f, 0.f, 0.f);
    if (act) {
        acc = *(const float4*)(g_acc + (size_t)node * NOUT + lane * 4);  // self
        bv = *(const float4*)(bias + lane * 4);
    }
    int i = beg;
    for (; i + 4 <= end; i += 4) {
        int s0 = g_esrc[i], s1 = g_esrc[i + 1], s2 = g_esrc[i + 2], s3 = g_esrc[i + 3];
        if (act) {
            float4 v0 = *(const float4*)(g_acc + (size_t)s0 * NOUT + lane * 4);
            float4 v1 = *(const float4*)(g_acc + (size_t)s1 * NOUT + lane * 4);
            float4 v2 = *(const float4*)(g_acc + (size_t)s2 * NOUT + lane * 4);
            float4 v3 = *(const float4*)(g_acc + (size_t)s3 * NOUT + lane * 4);
            acc.x += v0.x + v1.x + v2.x + v3.x;
            acc.y += v0.y + v1.y + v2.y + v3.y;
            acc.z += v0.z + v1.z + v2.z + v3.z;
            acc.w += v0.w + v1.w + v2.w + v3.w;
        }
    }
    for (; i < end; i++) {
        int s = g_esrc[i];
        if (act) {
            float4 v = *(const float4*)(g_acc + (size_t)s * NOUT + lane * 4);
            acc.x += v.x; acc.y += v.y; acc.z += v.z; acc.w += v.w;
        }
    }
    if (act) {
        acc.x += bv.x; acc.y += bv.y; acc.z += bv.z; acc.w += bv.w;
        if (RELU) {
            acc.x = fmaxf(acc.x, 0.f); acc.y = fmaxf(acc.y, 0.f);
            acc.z = fmaxf(acc.z, 0.f); acc.w = fmaxf(acc.w, 0.f);
        }
        float* outp = sel_out<OUTSEL>(out_p);
        *(float4*)(outp + (size_t)node * NOUT + lane * 4) = acc;
    }
}

// ---------------------------------------------------------------------------
extern "C" void kernel_launch(void* const* d_in, const int* in_sizes, int n_in,
                              void* d_out, int out_size) {
    const float* x  = (const float*)d_in[0];
    const int* src  = (const int*)d_in[1];
    const int* dst  = (const int*)d_in[2];
    const float* W0 = (const float*)d_in[3];
    const float* b0 = (const float*)d_in[4];
    const float* W1 = (const float*)d_in[5];
    const float* b1 = (const float*)d_in[6];
    const float* W2 = (const float*)d_in[7];
    const float* b2 = (const float*)d_in[8];
    float* out = (float*)d_out;
    int n_edges = in_sizes[1];

    constexpr int SMEM_BIG   = (64 * 132 + 128 * 132) * 4;  // 101376 B -> 2 CTA/SM
    constexpr int SMEM_SMALL = (64 * 132 + 64 * 132) * 4;   //  67584 B
    static cudaStream_t s1 = nullptr;
    static cudaEvent_t ev_fork = nullptr, ev_join = nullptr;
    if (!s1) {
        cudaFuncSetAttribute(gcn_gemm_kernel<0, 128, 8>,
                             cudaFuncAttributeMaxDynamicSharedMemorySize, SMEM_BIG);
        cudaFuncSetAttribute(gcn_gemm_kernel<1, 128, 8>,
                             cudaFuncAttributeMaxDynamicSharedMemorySize, SMEM_BIG);
        cudaFuncSetAttribute(gcn_gemm_kernel<2, 64, 4>,
                             cudaFuncAttributeMaxDynamicSharedMemorySize, SMEM_SMALL);
        cudaStreamCreateWithFlags(&s1, cudaStreamNonBlocking);
        cudaEventCreateWithFlags(&ev_fork, cudaEventDisableTiming);
        cudaEventCreateWithFlags(&ev_join, cudaEventDisableTiming);
    }

    void* cnt_ptr = nullptr;
    cudaGetSymbolAddress(&cnt_ptr, g_cnt);

    int hist_blocks = ((n_edges + 3) / 4 + 255) / 256;
    int gath_blocks = (N_NODES + 7) / 8;
    int gemm_blocks = (N_NODES + 63) / 64;

    // Fork: CSR build on s1, concurrent with GEMM0 on the origin stream.
    cudaEventRecord(ev_fork, 0);
    cudaStreamWaitEvent(s1, ev_fork, 0);
    cudaMemsetAsync(cnt_ptr, 0, N_NODES * sizeof(int), s1);
    gcn_hist_kernel<<<hist_blocks, 256, 0, s1>>>(dst, n_edges);
    gcn_scanA_kernel<<<SCAN_NBLK, SCAN_BLK, 0, s1>>>();
    gcn_scanB_kernel<<<SCAN_NBLK, SCAN_BLK, 0, s1>>>();
    gcn_fill_kernel<<<hist_blocks, 256, 0, s1>>>(src, dst, n_edges);
    cudaEventRecord(ev_join, s1);

    // GEMM0 (independent of CSR): z = x W0^T
    gcn_gemm_kernel<0, 128, 8><<<gemm_blocks, 256, SMEM_BIG>>>(x, W0, D, D);
    // Join CSR before the first gather.
    cudaStreamWaitEvent(0, ev_join, 0);

    // Layer 0 gather: h1 = relu(z + A z + b0) -> g_buf0
    gcn_gather_kernel<1, 128, true><<<gath_blocks, 256>>>(b0, nullptr);
    // Layer 1: z = h1 W1^T ; h2 = relu(z + A z + b1) -> g_buf1
    gcn_gemm_kernel<1, 128, 8><<<gemm_blocks, 256, SMEM_BIG>>>(nullptr, W1, D, D);
    gcn_gather_kernel<2, 128, true><<<gath_blocks, 256>>>(b1, nullptr);
    // Layer 2 (head): z = h2 W2^T (40-wide) ; out = z + A z + b2
    gcn_gemm_kernel<2, 64, 4><<<gemm_blocks, 256, SMEM_SMALL>>>(
        nullptr, W2, N_CLASSES, N_CLASSES);
    gcn_gather_kernel<0, N_CLASSES, false><<<gath_blocks, 256>>>(b2, out);
}